// round 3
// baseline (speedup 1.0000x reference)
#include <cuda_runtime.h>

// Problem constants
#define BP   128          // B*P
#define SEQ  1024         // S
#define DIM  1024         // D
#define NH   16           // heads
#define DH   64           // depth per head
#define SCALE 0.125f      // 1/sqrt(64)
#define SIGMA 0.1f

// ---------------- scratch (device globals; no allocation allowed) ------------
__device__ float g_qp[BP * DIM];
__device__ float g_kp[BP * DIM];
__device__ float g_vp[BP * DIM];
__device__ float g_part[32 * BP * DIM];   // per-s-chunk exp-weighted V partials
__device__ float g_zsum[32 * BP * NH];    // per-s-chunk exp sums
__device__ float g_zh[BP * DIM];          // merged attention output (mean_z)

// ---------------- projection GEMM: out[m][n] = x[m][:]·W[:][n] + b[n] + SIGMA*nz[m][n]
__device__ __forceinline__ void proj_body(const float* __restrict__ x,
                                          const float* __restrict__ W,
                                          const float* __restrict__ bias,
                                          const float* __restrict__ nz,
                                          float* __restrict__ out,
                                          int colBase)
{
    __shared__ float xs[32][132];   // [k][m], padded
    __shared__ float ws[32][32];    // [k][n]

    const int tid = threadIdx.x;          // 0..127
    const int tx  = tid & 3;              // 4 col-groups of 8
    const int ty  = tid >> 2;             // 32 row-groups of 4

    float acc[4][8];
#pragma unroll
    for (int i = 0; i < 4; i++)
#pragma unroll
        for (int j = 0; j < 8; j++) acc[i][j] = 0.f;

    for (int kk = 0; kk < DIM; kk += 32) {
#pragma unroll
        for (int r = 0; r < 8; r++) {
            int i  = tid + r * 128;
            int m  = i >> 3;
            int kq = (i & 7) << 2;
            float4 v = *reinterpret_cast<const float4*>(x + m * DIM + kk + kq);
            xs[kq + 0][m] = v.x;
            xs[kq + 1][m] = v.y;
            xs[kq + 2][m] = v.z;
            xs[kq + 3][m] = v.w;
        }
#pragma unroll
        for (int r = 0; r < 2; r++) {
            int i  = tid + r * 128;
            int k  = i >> 3;
            int nq = (i & 7) << 2;
            *reinterpret_cast<float4*>(&ws[k][nq]) =
                *reinterpret_cast<const float4*>(W + (kk + k) * DIM + colBase + nq);
        }
        __syncthreads();

#pragma unroll 8
        for (int k = 0; k < 32; k++) {
            float4 a  = *reinterpret_cast<const float4*>(&xs[k][ty << 2]);
            float4 b0 = *reinterpret_cast<const float4*>(&ws[k][(tx << 3)]);
            float4 b1 = *reinterpret_cast<const float4*>(&ws[k][(tx << 3) + 4]);
            float av[4] = {a.x, a.y, a.z, a.w};
            float bv[8] = {b0.x, b0.y, b0.z, b0.w, b1.x, b1.y, b1.z, b1.w};
#pragma unroll
            for (int i = 0; i < 4; i++)
#pragma unroll
                for (int j = 0; j < 8; j++) acc[i][j] += av[i] * bv[j];
        }
        __syncthreads();
    }

    int n0 = colBase + (tx << 3);
    float4 bL = *reinterpret_cast<const float4*>(bias + n0);
    float4 bH = *reinterpret_cast<const float4*>(bias + n0 + 4);
#pragma unroll
    for (int i = 0; i < 4; i++) {
        int m = (ty << 2) + i;
        float4 nL = *reinterpret_cast<const float4*>(nz + m * DIM + n0);
        float4 nH = *reinterpret_cast<const float4*>(nz + m * DIM + n0 + 4);
        float4 rL, rH;
        rL.x = acc[i][0] + bL.x + SIGMA * nL.x;
        rL.y = acc[i][1] + bL.y + SIGMA * nL.y;
        rL.z = acc[i][2] + bL.z + SIGMA * nL.z;
        rL.w = acc[i][3] + bL.w + SIGMA * nL.w;
        rH.x = acc[i][4] + bH.x + SIGMA * nH.x;
        rH.y = acc[i][5] + bH.y + SIGMA * nH.y;
        rH.z = acc[i][6] + bH.z + SIGMA * nH.z;
        rH.w = acc[i][7] + bH.w + SIGMA * nH.w;
        *reinterpret_cast<float4*>(out + m * DIM + n0)     = rL;
        *reinterpret_cast<float4*>(out + m * DIM + n0 + 4) = rH;
    }
}

__global__ void __launch_bounds__(128)
proj3_kernel(const float* __restrict__ q, const float* __restrict__ k,
             const float* __restrict__ v,
             const float* __restrict__ Wq, const float* __restrict__ Wk,
             const float* __restrict__ Wv,
             const float* __restrict__ bq, const float* __restrict__ bk,
             const float* __restrict__ bv,
             const float* __restrict__ nq, const float* __restrict__ nk,
             const float* __restrict__ nv)
{
    int mat = blockIdx.y;
    const float* x = (mat == 0) ? q  : (mat == 1) ? k  : v;
    const float* W = (mat == 0) ? Wq : (mat == 1) ? Wk : Wv;
    const float* b = (mat == 0) ? bq : (mat == 1) ? bk : bv;
    const float* n = (mat == 0) ? nq : (mat == 1) ? nk : nv;
    float* o       = (mat == 0) ? g_qp : (mat == 1) ? g_kp : g_vp;
    proj_body(x, W, b, n, o, blockIdx.x * 32);
}

__global__ void __launch_bounds__(128)
projZ_kernel(const float* __restrict__ Wz, const float* __restrict__ bz,
             const float* __restrict__ nz, float* __restrict__ z_out)
{
    proj_body(g_zh, Wz, bz, nz, z_out, blockIdx.x * 32);
}

// ---------------- fused K/V copy + logits + exp-weighted partials -----------
// grid (32 s-chunks, 128 bp), 256 threads. Phase K: stream 32 K rows
// (slot-substituting row t), compute per-head logits. Phase V: stream 32 V
// rows with unnormalized weights w = exp(logit) accumulated into partials.
// No softmax barrier: normalization happens in combine_kernel.
__global__ void __launch_bounds__(256)
fusedKV_kernel(const float* __restrict__ K, const float* __restrict__ V,
               float* __restrict__ Kout, float* __restrict__ Vout,
               float* __restrict__ logits, const int* __restrict__ tptr)
{
    const int bp  = blockIdx.y;
    const int s0  = blockIdx.x * 32;
    const int tid = threadIdx.x;
    const int t   = *tptr;

    __shared__ float pds[32][256];   // per-s, per-thread partial dot
    __shared__ float wa[32][NH];     // exp(logit) per s-row, per head

    float4 q4 = *reinterpret_cast<const float4*>(g_qp + bp * DIM + (tid << 2));
    const float* kprow = g_kp + bp * DIM;
    const float* vprow = g_vp + bp * DIM;
    const float* Kb = K    + (size_t)bp * SEQ * DIM;
    float*       KOb = Kout + (size_t)bp * SEQ * DIM;
    const float* Vb = V    + (size_t)bp * SEQ * DIM;
    float*       VOb = Vout + (size_t)bp * SEQ * DIM;

    // --- Phase K: batched 4-load / 4-store for MLP ---
    for (int slb = 0; slb < 32; slb += 4) {
        float4 vv[4];
#pragma unroll
        for (int j = 0; j < 4; j++) {
            int s = s0 + slb + j;
            const float* src = (s == t) ? kprow : (Kb + (size_t)s * DIM);
            vv[j] = *reinterpret_cast<const float4*>(src + (tid << 2));
        }
#pragma unroll
        for (int j = 0; j < 4; j++) {
            int s = s0 + slb + j;
            *reinterpret_cast<float4*>(KOb + (size_t)s * DIM + (tid << 2)) = vv[j];
            pds[slb + j][tid] = vv[j].x * q4.x + vv[j].y * q4.y
                              + vv[j].z * q4.z + vv[j].w * q4.w;
        }
    }
    __syncthreads();

    // logits + unnormalized weights (16 heads x 32 s)
    for (int i = tid; i < 512; i += 256) {
        int h  = i & 15;
        int sl = i >> 4;
        float sum = 0.f;
#pragma unroll
        for (int j = 0; j < 16; j++) sum += pds[sl][(h << 4) + j];
        float l = sum * SCALE;
        logits[((size_t)(bp * NH + h)) * SEQ + s0 + sl] = l;
        wa[sl][h] = __expf(l);
    }
    __syncthreads();

    // per-chunk exp sums (threads 0..15, one head each)
    if (tid < NH) {
        float z = 0.f;
#pragma unroll
        for (int sl = 0; sl < 32; sl++) z += wa[sl][tid];
        g_zsum[((size_t)blockIdx.x * BP + bp) * NH + tid] = z;
    }

    // --- Phase V: batched, with exp-weighted accumulation ---
    const int h = tid >> 4;
    float4 acc = make_float4(0.f, 0.f, 0.f, 0.f);
    for (int slb = 0; slb < 32; slb += 4) {
        float4 vv[4];
#pragma unroll
        for (int j = 0; j < 4; j++) {
            int s = s0 + slb + j;
            const float* src = (s == t) ? vprow : (Vb + (size_t)s * DIM);
            vv[j] = *reinterpret_cast<const float4*>(src + (tid << 2));
        }
#pragma unroll
        for (int j = 0; j < 4; j++) {
            int s = s0 + slb + j;
            *reinterpret_cast<float4*>(VOb + (size_t)s * DIM + (tid << 2)) = vv[j];
            float a = wa[slb + j][h];
            acc.x += a * vv[j].x; acc.y += a * vv[j].y;
            acc.z += a * vv[j].z; acc.w += a * vv[j].w;
        }
    }
    *reinterpret_cast<float4*>(g_part + ((size_t)blockIdx.x * BP + bp) * DIM + (tid << 2)) = acc;
}

// ---------------- softmax (attn output only; off the zh critical path) ------
__global__ void __launch_bounds__(256)
softmax_kernel(float* __restrict__ attn)
{
    int row  = blockIdx.x * 8 + (threadIdx.x >> 5);   // 2048 rows
    int lane = threadIdx.x & 31;
    float* p = attn + (size_t)row * SEQ;

    float v[32];
    float m = -1e30f;
#pragma unroll
    for (int i = 0; i < 32; i++) { v[i] = p[lane + (i << 5)]; m = fmaxf(m, v[i]); }
#pragma unroll
    for (int o = 16; o > 0; o >>= 1) m = fmaxf(m, __shfl_xor_sync(0xffffffffu, m, o));
    float sum = 0.f;
#pragma unroll
    for (int i = 0; i < 32; i++) { v[i] = __expf(v[i] - m); sum += v[i]; }
#pragma unroll
    for (int o = 16; o > 0; o >>= 1) sum += __shfl_xor_sync(0xffffffffu, sum, o);
    float inv = 1.f / sum;
#pragma unroll
    for (int i = 0; i < 32; i++) p[lane + (i << 5)] = v[i] * inv;
}

// ---------------- combine: normalize chunk partials into g_zh ---------------
__global__ void __launch_bounds__(256)
combine_kernel()
{
    const int bp  = blockIdx.x;
    const int tid = threadIdx.x;

    __shared__ float zinv[NH];
    if (tid < NH) {
        float z = 0.f;
#pragma unroll
        for (int c = 0; c < 32; c++) z += g_zsum[((size_t)c * BP + bp) * NH + tid];
        zinv[tid] = 1.f / z;
    }
    __syncthreads();

    const int h = tid >> 4;   // head of cols 4t..4t+3
    float4 acc = make_float4(0.f, 0.f, 0.f, 0.f);
#pragma unroll
    for (int c = 0; c < 32; c++) {
        float4 p = *reinterpret_cast<const float4*>(
            g_part + ((size_t)c * BP + bp) * DIM + (tid << 2));
        acc.x += p.x; acc.y += p.y; acc.z += p.z; acc.w += p.w;
    }
    float s = zinv[h];
    acc.x *= s; acc.y *= s; acc.z *= s; acc.w *= s;
    *reinterpret_cast<float4*>(g_zh + (size_t)bp * DIM + (tid << 2)) = acc;
}

// ---------------- launch ----------------------------------------------------
extern "C" void kernel_launch(void* const* d_in, const int* in_sizes, int n_in,
                              void* d_out, int out_size)
{
    const float* q   = (const float*)d_in[0];
    const float* k   = (const float*)d_in[1];
    const float* v   = (const float*)d_in[2];
    const float* Kin = (const float*)d_in[3];
    const float* Vin = (const float*)d_in[4];
    const float* Wq  = (const float*)d_in[5];
    const float* bq  = (const float*)d_in[6];
    const float* Wk  = (const float*)d_in[7];
    const float* bk  = (const float*)d_in[8];
    const float* Wv  = (const float*)d_in[9];
    const float* bv  = (const float*)d_in[10];
    const float* Wz  = (const float*)d_in[11];
    const float* bz  = (const float*)d_in[12];
    const float* nq  = (const float*)d_in[13];
    const float* nk  = (const float*)d_in[14];
    const float* nv  = (const float*)d_in[15];
    const float* nz  = (const float*)d_in[16];
    const int* tstep = (const int*)d_in[17];

    float* out   = (float*)d_out;
    float* z_out = out;                                       // 128*1024
    float* K_out = out + (size_t)BP * DIM;                    // 128*1024*1024
    float* V_out = K_out + (size_t)BP * SEQ * DIM;
    float* attn  = V_out + (size_t)BP * SEQ * DIM;            // 128*16*1024

    // 1. projections q/k/v (+bias +sigma*noise)
    proj3_kernel<<<dim3(32, 3), 128>>>(q, k, v, Wq, Wk, Wv, bq, bk, bv, nq, nk, nv);
    // 2. fused K+V copy (slot write at t) + logits + exp-weighted partials
    fusedKV_kernel<<<dim3(32, BP), 256>>>(Kin, Vin, K_out, V_out, attn, tstep);
    // 3. softmax of attn output (independent of zh path)
    softmax_kernel<<<256, 256>>>(attn);
    // 4. normalize partials -> zh
    combine_kernel<<<BP, 256>>>();
    // 5. output projection z
    projZ_kernel<<<dim3(32, 1), 128>>>(Wz, bz, nz, z_out);
}